// round 15
// baseline (speedup 1.0000x reference)
#include <cuda_runtime.h>

#define BATCH 262144
#define DIM   128
#define K     10

#define T1        128
#define TILE_ROWS 128                    // 1 row per thread
#define NTILES    (BATCH / TILE_ROWS)    // 2048
#define NBLK1     NTILES                 // 1 tile per block
#define NCHUNK    8                      // 16 dims per chunk
#define NSTAGE    3                      // ring depth
#define CH_F4     4                      // float4 per row per chunk
#define BUF_F4    (TILE_ROWS * CH_F4)    // 512 float4 = 8 KB

#define NBLK2 1024
#define T2    256
#define RPB2  (BATCH / NBLK2)            // 256

// Scratch (no allocs). g_part fully overwritten every launch.
__device__ float g_part[NBLK1][K];
__device__ float g_invf[K];

typedef unsigned long long u64;

__device__ __forceinline__ void unpack2(u64 v, float& lo, float& hi) {
    asm("mov.b64 {%0, %1}, %2;" : "=f"(lo), "=f"(hi) : "l"(v));
}
__device__ __forceinline__ void fma2(u64& acc, u64 a, u64 b) {
    asm("fma.rn.f32x2 %0, %1, %2, %0;" : "+l"(acc) : "l"(a), "l"(b));
}
__device__ __forceinline__ void cp_async16(unsigned smem_addr, const void* g) {
    asm volatile("cp.async.cg.shared.global [%0], [%1], 16;"
                 :: "r"(smem_addr), "l"(g) : "memory");
}
__device__ __forceinline__ void cp_commit() {
    asm volatile("cp.async.commit_group;" ::: "memory");
}
__device__ __forceinline__ void cp_wait1() {
    asm volatile("cp.async.wait_group 1;" ::: "memory");
}
__device__ __forceinline__ void cp_wait0() {
    asm volatile("cp.async.wait_group 0;" ::: "memory");
}

// Kernel 1: q = rownorm( 1/(1 + ||z - mu||^2) ), per-block colsum partials.
// 1 row/thread (low regs -> 6 blocks/SM resident); 3-stage cp.async ring over
// 8KB chunks, one barrier per chunk: wait(k) -> sync -> stage(k+2) -> compute(k).
__global__ void __launch_bounds__(T1, 6) k_q(
    const float* __restrict__ z,
    const float* __restrict__ c,
    float* __restrict__ qout)
{
    __shared__ float4 s_buf[NSTAGE][BUF_F4];   // 3 x 8 KB
    __shared__ float4 s_c[K][DIM / 4];         // 5120 B
    __shared__ float  s_cn[K];
    __shared__ float  s_part[4][K];

    const int tid  = threadIdx.x;
    const int lane = tid & 31;
    const int wrp  = tid >> 5;
    const int skey = (tid >> 1) & 3;           // swizzle key for this row
    const unsigned sb = (unsigned)__cvta_generic_to_shared(&s_buf[0][0]);

    for (int i = tid; i < K * DIM / 4; i += T1)
        ((float4*)s_c)[i] = ((const float4*)c)[i];
    __syncthreads();
    if (tid < K) {
        float s = 0.0f;
        #pragma unroll
        for (int d = 0; d < DIM / 4; d++) {
            float4 v = s_c[tid][d];
            s = fmaf(v.x, v.x, fmaf(v.y, v.y, fmaf(v.z, v.z, fmaf(v.w, v.w, s))));
        }
        s_cn[tid] = s;
    }
    __syncthreads();

    const int t = blockIdx.x;                  // exactly one tile per block

    // Stage chunk k into ring slot: 128 rows x 64B, swizzled dst.
    auto stage = [&](int slot, int k) {
        const float4* zt = (const float4*)z + (size_t)t * TILE_ROWS * 32 + k * CH_F4;
        const unsigned base = sb + (unsigned)slot * (BUF_F4 * 16);
        #pragma unroll
        for (int k2 = 0; k2 < BUF_F4 / T1; k2++) {   // 4 per thread
            const int g   = k2 * T1 + tid;           // [0, 512)
            const int row = g >> 2;
            const int i   = g & 3;
            cp_async16(base + (unsigned)(row * CH_F4 + (i ^ ((row >> 1) & 3))) * 16,
                       zt + (size_t)row * 32 + i);
        }
        cp_commit();
    };

    const ulonglong2* sc2 = reinterpret_cast<const ulonglong2*>(s_c);

    stage(0, 0);
    stage(1, 1);

    u64 dot[K], zn = 0ull;
    #pragma unroll
    for (int j = 0; j < K; j++) dot[j] = 0ull;

    #pragma unroll
    for (int k = 0; k < NCHUNK; k++) {
        if (k < NCHUNK - 1) cp_wait1(); else cp_wait0();
        __syncthreads();                 // chunk k visible; slot (k+2)%3 free
        if (k + 2 < NCHUNK) stage((k + 2) % NSTAGE, k + 2);

        const ulonglong2* b2 =
            reinterpret_cast<const ulonglong2*>(&s_buf[k % NSTAGE][0]);
        #pragma unroll
        for (int i = 0; i < CH_F4; i++) {
            ulonglong2 a = b2[tid * CH_F4 + (i ^ skey)];
            fma2(zn, a.x, a.x); fma2(zn, a.y, a.y);
            #pragma unroll
            for (int j = 0; j < K; j++) {
                ulonglong2 cc = sc2[j * (DIM / 4) + k * CH_F4 + i];
                fma2(dot[j], a.x, cc.x); fma2(dot[j], a.y, cc.y);
            }
        }
    }

    float lo, hi;
    unpack2(zn, lo, hi);
    const float zz1 = 1.0f + (lo + hi);

    float q[K], rsum = 0.0f;
    #pragma unroll
    for (int j = 0; j < K; j++) {
        unpack2(dot[j], lo, hi);
        const float d = lo + hi;
        const float v = __fdividef(1.0f, fmaf(-2.0f, d, zz1 + s_cn[j]));
        q[j] = v; rsum += v;
    }
    const float inv = __fdividef(1.0f, rsum);

    const int row = t * TILE_ROWS + tid;
    float* orow = qout + (size_t)row * K;
    #pragma unroll
    for (int j = 0; j < K; j++) q[j] *= inv;
    #pragma unroll
    for (int m = 0; m < 5; m++) {
        float2 v; v.x = q[2 * m]; v.y = q[2 * m + 1];
        *(float2*)(orow + 2 * m) = v;
    }

    // Block colsum partial -> g_part[blockIdx.x]
    #pragma unroll
    for (int j = 0; j < K; j++) {
        float v = q[j];
        #pragma unroll
        for (int m = 16; m > 0; m >>= 1) v += __shfl_xor_sync(0xFFFFFFFFu, v, m);
        if (lane == 0) s_part[wrp][j] = v;
    }
    __syncthreads();
    if (tid < K)
        g_part[blockIdx.x][tid] =
            s_part[0][tid] + s_part[1][tid] + s_part[2][tid] + s_part[3][tid];
}

// Finalize: reduce 2048 colsum partials -> g_invf. One block, 512 threads.
__global__ __launch_bounds__(512) void k_fin() {
    __shared__ float s_w[16][K];
    const int tid  = threadIdx.x;
    const int lane = tid & 31;
    const int wrp  = tid >> 5;

    #pragma unroll
    for (int j = 0; j < K; j++) {
        float v = g_part[tid][j] + g_part[tid + 512][j]
                + g_part[tid + 1024][j] + g_part[tid + 1536][j];
        #pragma unroll
        for (int m = 16; m > 0; m >>= 1) v += __shfl_xor_sync(0xFFFFFFFFu, v, m);
        if (lane == 0) s_w[wrp][j] = v;
    }
    __syncthreads();
    if (tid < K) {
        float s = 0.0f;
        #pragma unroll
        for (int w = 0; w < 16; w++) s += s_w[w][tid];
        g_invf[tid] = __fdividef(1.0f, s);
    }
}

// Kernel 2 (measured ~7us): p = rownorm( q^2 * g_invf ).
__global__ __launch_bounds__(T2) void k_p(
    const float* __restrict__ q,
    float* __restrict__ p)
{
    __shared__ float s_q[RPB2 * K];
    __shared__ float s_p[RPB2 * K];
    __shared__ float s_inv[K];

    const int tid = threadIdx.x;
    if (tid < K) s_inv[tid] = g_invf[tid];

    const float4* qg = (const float4*)(q + (size_t)blockIdx.x * RPB2 * K);
    #pragma unroll
    for (int i = 0; i < (RPB2 * K / 4 + T2 - 1) / T2; i++) {
        const int idx = i * T2 + tid;
        if (idx < RPB2 * K / 4) ((float4*)s_q)[idx] = qg[idx];
    }
    __syncthreads();

    float w[K], s = 0.0f;
    const float* qr = s_q + tid * K;
    #pragma unroll
    for (int j = 0; j < K; j++) {
        float v = qr[j];
        w[j] = v * v * s_inv[j];
        s += w[j];
    }
    const float inv = __fdividef(1.0f, s);
    float* pr = s_p + tid * K;
    #pragma unroll
    for (int j = 0; j < K; j++) pr[j] = w[j] * inv;
    __syncthreads();

    float4* pg = (float4*)(p + (size_t)blockIdx.x * RPB2 * K);
    #pragma unroll
    for (int i = 0; i < (RPB2 * K / 4 + T2 - 1) / T2; i++) {
        const int idx = i * T2 + tid;
        if (idx < RPB2 * K / 4) pg[idx] = ((const float4*)s_p)[idx];
    }
}

extern "C" void kernel_launch(void* const* d_in, const int* in_sizes, int n_in,
                              void* d_out, int out_size) {
    const float* z = (const float*)d_in[0];
    const float* c = (const float*)d_in[1];
    float* qout = (float*)d_out;
    float* pout = (float*)d_out + (size_t)BATCH * K;

    k_q<<<NBLK1, T1>>>(z, c, qout);
    k_fin<<<1, 512>>>();
    k_p<<<NBLK2, T2>>>(qout, pout);
}

// round 16
// speedup vs baseline: 1.1477x; 1.1477x over previous
#include <cuda_runtime.h>

#define BATCH 262144
#define DIM   128
#define K     10

#define T1        128
#define TILE_ROWS 256                    // 2 rows per thread
#define NTILES    (BATCH / TILE_ROWS)    // 1024
#define NBLK1     NTILES                 // 1 tile per block
#define NCHUNK    8                      // 16 dims per chunk
#define NSTAGE    3                      // ring depth
#define CH_F4     4                      // float4 per row per chunk
#define BUF_F4    (TILE_ROWS * CH_F4)    // 1024 float4 = 16 KB per slot

#define NBLK2 1024
#define T2    256
#define RPB2  (BATCH / NBLK2)            // 256

// Scratch (no allocs). g_part fully overwritten every launch.
__device__ float g_part[NBLK1][K];
__device__ float g_invf[K];

typedef unsigned long long u64;

__device__ __forceinline__ void unpack2(u64 v, float& lo, float& hi) {
    asm("mov.b64 {%0, %1}, %2;" : "=f"(lo), "=f"(hi) : "l"(v));
}
__device__ __forceinline__ void fma2(u64& acc, u64 a, u64 b) {
    asm("fma.rn.f32x2 %0, %1, %2, %0;" : "+l"(acc) : "l"(a), "l"(b));
}
__device__ __forceinline__ void cp_async16(unsigned smem_addr, const void* g) {
    asm volatile("cp.async.cg.shared.global [%0], [%1], 16;"
                 :: "r"(smem_addr), "l"(g) : "memory");
}
__device__ __forceinline__ void cp_commit() {
    asm volatile("cp.async.commit_group;" ::: "memory");
}
__device__ __forceinline__ void cp_wait2() {
    asm volatile("cp.async.wait_group 2;" ::: "memory");
}
__device__ __forceinline__ void cp_wait1() {
    asm volatile("cp.async.wait_group 1;" ::: "memory");
}
__device__ __forceinline__ void cp_wait0() {
    asm volatile("cp.async.wait_group 0;" ::: "memory");
}

// Kernel 1: q = rownorm( 1/(1 + ||z - mu||^2) ), per-block colsum partials.
// 2 rows/thread. WARP-PRIVATE 3-stage cp.async ring: each warp stages exactly
// the 64 rows its threads read -> per-warp wait_group, ZERO barriers in the
// main loop. Warps run decoupled; scheduler always has ready work.
__global__ __launch_bounds__(T1) void k_q(
    const float* __restrict__ z,
    const float* __restrict__ c,
    float* __restrict__ qout)
{
    __shared__ float4 s_buf[NSTAGE][BUF_F4];   // 3 x 16 KB
    __shared__ float4 s_c[K][DIM / 4];         // 5120 B
    __shared__ float  s_cn[K];
    __shared__ float  s_part[4][K];

    const int tid  = threadIdx.x;
    const int lane = tid & 31;
    const int wrp  = tid >> 5;
    const int skey = (tid >> 1) & 3;           // swizzle key; same for tid+128
    const unsigned sb = (unsigned)__cvta_generic_to_shared(&s_buf[0][0]);

    for (int i = tid; i < K * DIM / 4; i += T1)
        ((float4*)s_c)[i] = ((const float4*)c)[i];
    __syncthreads();
    if (tid < K) {
        float s = 0.0f;
        #pragma unroll
        for (int d = 0; d < DIM / 4; d++) {
            float4 v = s_c[tid][d];
            s = fmaf(v.x, v.x, fmaf(v.y, v.y, fmaf(v.z, v.z, fmaf(v.w, v.w, s))));
        }
        s_cn[tid] = s;
    }
    __syncthreads();

    const int t = blockIdx.x;                  // exactly one tile per block

    // Warp-private stage of chunk k: rows {w*32..w*32+31} U {+128}, 64B each.
    // 8 cp.async per lane; per step 8 consecutive rows x 64B (2 sectors/row).
    auto stage = [&](int slot, int k) {
        const float4* zt = (const float4*)z + (size_t)t * TILE_ROWS * 32 + k * CH_F4;
        const unsigned base = sb + (unsigned)slot * (BUF_F4 * 16);
        #pragma unroll
        for (int k2 = 0; k2 < 8; k2++) {
            const int g  = k2 * 32 + lane;     // [0, 256) within warp
            const int rl = g >> 2;             // local row 0..63
            const int i  = g & 3;
            const int row = wrp * 32 + ((rl < 32) ? rl : (96 + rl));
            cp_async16(base + (unsigned)(row * CH_F4 + (i ^ ((row >> 1) & 3))) * 16,
                       zt + (size_t)row * 32 + i);
        }
        cp_commit();
    };

    const ulonglong2* sc2 = reinterpret_cast<const ulonglong2*>(s_c);

    stage(0, 0);
    stage(1, 1);

    u64 dot0[K], dot1[K], zn0 = 0ull, zn1 = 0ull;
    #pragma unroll
    for (int j = 0; j < K; j++) { dot0[j] = 0ull; dot1[j] = 0ull; }

    #pragma unroll
    for (int k = 0; k < NCHUNK; k++) {
        if (k + 2 < NCHUNK) stage((k + 2) % NSTAGE, k + 2);
        // Wait until this warp's chunk k has landed (counts resolved statically).
        if (k + 2 < NCHUNK)      cp_wait2();
        else if (k + 1 < NCHUNK) cp_wait1();
        else                     cp_wait0();

        const ulonglong2* b2 =
            reinterpret_cast<const ulonglong2*>(&s_buf[k % NSTAGE][0]);
        #pragma unroll
        for (int i = 0; i < CH_F4; i++) {
            const int isw = i ^ skey;
            ulonglong2 a0 = b2[tid * CH_F4 + isw];
            ulonglong2 a1 = b2[(tid + 128) * CH_F4 + isw];
            fma2(zn0, a0.x, a0.x); fma2(zn0, a0.y, a0.y);
            fma2(zn1, a1.x, a1.x); fma2(zn1, a1.y, a1.y);
            #pragma unroll
            for (int j = 0; j < K; j++) {
                ulonglong2 cc = sc2[j * (DIM / 4) + k * CH_F4 + i];
                fma2(dot0[j], a0.x, cc.x); fma2(dot0[j], a0.y, cc.y);
                fma2(dot1[j], a1.x, cc.x); fma2(dot1[j], a1.y, cc.y);
            }
        }
    }

    float csum[K];
    #pragma unroll
    for (int j = 0; j < K; j++) csum[j] = 0.0f;

    float lo, hi;
    #pragma unroll
    for (int rr = 0; rr < 2; rr++) {
        unpack2(rr ? zn1 : zn0, lo, hi);
        const float zz1 = 1.0f + (lo + hi);
        float q[K], rsum = 0.0f;
        #pragma unroll
        for (int j = 0; j < K; j++) {
            unpack2(rr ? dot1[j] : dot0[j], lo, hi);
            const float d = lo + hi;
            const float v = __fdividef(1.0f, fmaf(-2.0f, d, zz1 + s_cn[j]));
            q[j] = v; rsum += v;
        }
        const float inv = __fdividef(1.0f, rsum);
        const int row = t * TILE_ROWS + rr * 128 + tid;
        float* orow = qout + (size_t)row * K;
        #pragma unroll
        for (int j = 0; j < K; j++) { q[j] *= inv; csum[j] += q[j]; }
        #pragma unroll
        for (int m = 0; m < 5; m++) {
            float2 v; v.x = q[2 * m]; v.y = q[2 * m + 1];
            *(float2*)(orow + 2 * m) = v;
        }
    }

    // Block colsum partial -> g_part[blockIdx.x]
    #pragma unroll
    for (int j = 0; j < K; j++) {
        float v = csum[j];
        #pragma unroll
        for (int m = 16; m > 0; m >>= 1) v += __shfl_xor_sync(0xFFFFFFFFu, v, m);
        if (lane == 0) s_part[wrp][j] = v;
    }
    __syncthreads();
    if (tid < K)
        g_part[blockIdx.x][tid] =
            s_part[0][tid] + s_part[1][tid] + s_part[2][tid] + s_part[3][tid];
}

// Finalize: reduce 1024 colsum partials -> g_invf. One block, 512 threads.
__global__ __launch_bounds__(512) void k_fin() {
    __shared__ float s_w[16][K];
    const int tid  = threadIdx.x;
    const int lane = tid & 31;
    const int wrp  = tid >> 5;

    #pragma unroll
    for (int j = 0; j < K; j++) {
        float v = g_part[tid][j] + g_part[tid + 512][j];
        #pragma unroll
        for (int m = 16; m > 0; m >>= 1) v += __shfl_xor_sync(0xFFFFFFFFu, v, m);
        if (lane == 0) s_w[wrp][j] = v;
    }
    __syncthreads();
    if (tid < K) {
        float s = 0.0f;
        #pragma unroll
        for (int w = 0; w < 16; w++) s += s_w[w][tid];
        g_invf[tid] = __fdividef(1.0f, s);
    }
}

// Kernel 2 (measured ~7us): p = rownorm( q^2 * g_invf ).
__global__ __launch_bounds__(T2) void k_p(
    const float* __restrict__ q,
    float* __restrict__ p)
{
    __shared__ float s_q[RPB2 * K];
    __shared__ float s_p[RPB2 * K];
    __shared__ float s_inv[K];

    const int tid = threadIdx.x;
    if (tid < K) s_inv[tid] = g_invf[tid];

    const float4* qg = (const float4*)(q + (size_t)blockIdx.x * RPB2 * K);
    #pragma unroll
    for (int i = 0; i < (RPB2 * K / 4 + T2 - 1) / T2; i++) {
        const int idx = i * T2 + tid;
        if (idx < RPB2 * K / 4) ((float4*)s_q)[idx] = qg[idx];
    }
    __syncthreads();

    float w[K], s = 0.0f;
    const float* qr = s_q + tid * K;
    #pragma unroll
    for (int j = 0; j < K; j++) {
        float v = qr[j];
        w[j] = v * v * s_inv[j];
        s += w[j];
    }
    const float inv = __fdividef(1.0f, s);
    float* pr = s_p + tid * K;
    #pragma unroll
    for (int j = 0; j < K; j++) pr[j] = w[j] * inv;
    __syncthreads();

    float4* pg = (float4*)(p + (size_t)blockIdx.x * RPB2 * K);
    #pragma unroll
    for (int i = 0; i < (RPB2 * K / 4 + T2 - 1) / T2; i++) {
        const int idx = i * T2 + tid;
        if (idx < RPB2 * K / 4) pg[idx] = ((const float4*)s_p)[idx];
    }
}

extern "C" void kernel_launch(void* const* d_in, const int* in_sizes, int n_in,
                              void* d_out, int out_size) {
    const float* z = (const float*)d_in[0];
    const float* c = (const float*)d_in[1];
    float* qout = (float*)d_out;
    float* pout = (float*)d_out + (size_t)BATCH * K;

    k_q<<<NBLK1, T1>>>(z, c, qout);
    k_fin<<<1, 512>>>();
    k_p<<<NBLK2, T2>>>(qout, pout);
}